// round 14
// baseline (speedup 1.0000x reference)
#include <cuda_runtime.h>
#include <cuda_fp16.h>
#include <cstdint>
#include <cstddef>

#define B_ 2048
#define T_ 200
#define D_ 4
#define H_ 256
#define G_ 1024
#define CL 8
#define THREADS 512
#define WCH 16384
#define CHB 8192
#define TILEB 32768

#define SW_OFF 0
#define RING_OFF 131072            // 12 slots * 8KB
#define SXW_OFF 229376             // Wx fp16 1KB
#define SXR_OFF 230400             // 2 * 512B x rows
#define SMB_OFF 231424             // 12 slot mbars + W mbar
#define SMEM_TOTAL 231536

__device__ __align__(128) __half g_W0[G_ * H_];
__device__ __align__(128) __half g_Wx0h[G_ * D_];
__device__ __align__(128) float  g_b0[G_];
__device__ __align__(128) __half g_W1[G_ * 2 * H_];
__device__ __align__(128) float  g_b1[G_];
__device__ __align__(128) __half g_zero[B_ * H_];
__device__ __align__(128) __half g_h1seq[(size_t)T_ * B_ * H_];  // [(t*32+slice)] 32KB tiles
__device__ __align__(128) __half g_h2a[B_ * H_];
__device__ __align__(128) __half g_h2b[B_ * H_];
__device__ __align__(128) float  g_h2f[B_ * H_];

__global__ void k_init() {
    int s = gridDim.x * blockDim.x;
    for (int i = blockIdx.x * blockDim.x + threadIdx.x; i < B_ * H_; i += s)
        g_zero[i] = __float2half(0.f);
}
__device__ __forceinline__ size_t swoffW(int r, int k) {
    int kc = k >> 6, cc = k & 63, g = cc >> 3, e = cc & 7;
    return (size_t)kc * WCH + r * 128 + ((g ^ (r & 7)) << 4) + e * 2;
}
__device__ __forceinline__ int col2row(int n) {
    int c = n & 31;
    int j = (n >> 5) * 8 + ((c >> 4) << 2) + ((c >> 1) & 3);
    int blk = (c >> 3) & 1, e = c & 1;
    int g = blk ? (e ? 3 : 2) : (e ? 1 : 0);
    return g * H_ + j;
}
__global__ void k_pack0(const float* __restrict__ Wi, const float* __restrict__ Wh,
                        const float* __restrict__ bi, const float* __restrict__ bh) {
    int s = gridDim.x * blockDim.x;
    for (int i = blockIdx.x * blockDim.x + threadIdx.x; i < G_ * H_; i += s) {
        int n = i >> 8, k = i & 255;
        int orow = col2row(n);
        int rank = n >> 7, r = n & 127;
        *(__half*)((char*)g_W0 + (size_t)rank * 65536 + swoffW(r, k)) = __float2half(Wh[orow * H_ + k]);
        if (k < D_) g_Wx0h[n * D_ + k] = __float2half(Wi[orow * D_ + k]);
        if (k == 0) g_b0[n] = bi[orow] + bh[orow];
    }
}
__global__ void k_pack1(const float* __restrict__ Wi, const float* __restrict__ Wh,
                        const float* __restrict__ bi, const float* __restrict__ bh) {
    int s = gridDim.x * blockDim.x;
    for (int i = blockIdx.x * blockDim.x + threadIdx.x; i < G_ * 512; i += s) {
        int n = i >> 9, k = i & 511;
        int orow = col2row(n);
        int rank = n >> 7, r = n & 127;
        float v = (k < H_) ? Wi[orow * H_ + k] : Wh[orow * H_ + (k - H_)];
        *(__half*)((char*)g_W1 + (size_t)rank * 131072 + swoffW(r, k)) = __float2half(v);
        if (k == 0) g_b1[n] = bi[orow] + bh[orow];
    }
}

__device__ __forceinline__ uint32_t smem_u32(const void* p) {
    uint32_t a;
    asm("{ .reg .u64 t; cvta.to.shared.u64 t, %1; cvt.u32.u64 %0, t; }" : "=r"(a) : "l"(p));
    return a;
}
__device__ __forceinline__ void clsync() {
    asm volatile("barrier.cluster.arrive.aligned;" ::: "memory");
    asm volatile("barrier.cluster.wait.aligned;" ::: "memory");
}
__device__ __forceinline__ float tanha_(float x) {
    float r; asm("tanh.approx.f32 %0, %1;" : "=f"(r) : "f"(x));
    return r;
}
__device__ __forceinline__ float siga_(float x) { return __fmaf_rn(tanha_(0.5f * x), 0.5f, 0.5f); }
__device__ __forceinline__ void mbar_init(uint32_t m, uint32_t c) {
    asm volatile("mbarrier.init.shared.b64 [%0], %1;" :: "r"(m), "r"(c) : "memory");
}
__device__ __forceinline__ void bulk_in(uint32_t sdst, const void* g, uint32_t bytes, uint32_t mb) {
    asm volatile("mbarrier.arrive.expect_tx.shared.b64 _, [%0], %1;" :: "r"(mb), "r"(bytes) : "memory");
    asm volatile("cp.async.bulk.shared::cluster.global.mbarrier::complete_tx::bytes [%0], [%1], %2, [%3];"
                 :: "r"(sdst), "l"(g), "r"(bytes), "r"(mb) : "memory");
}
__device__ __forceinline__ void mbar_wait(uint32_t m, uint32_t par) {
    uint32_t done;
    asm volatile("{.reg .pred p; mbarrier.try_wait.parity.acquire.cta.shared::cta.b64 p, [%1], %2; selp.b32 %0,1,0,p;}"
                 : "=r"(done) : "r"(m), "r"(par) : "memory");
    if (!done) {
        asm volatile("{.reg .pred P1;\nWL_%=:\n"
                     "mbarrier.try_wait.parity.acquire.cta.shared::cta.b64 P1, [%0], %1, 0x989680;\n"
                     "@P1 bra.uni WD_%=;\nbra.uni WL_%=;\nWD_%=:\n}"
                     :: "r"(m), "r"(par) : "memory");
    }
}
__device__ __forceinline__ void load4h(const __half* p, float f[4]) {
    uint2 u = *(const uint2*)p;
    __half2 h0 = *reinterpret_cast<__half2*>(&u.x);
    __half2 h1 = *reinterpret_cast<__half2*>(&u.y);
    float2 a = __half22float2(h0), b = __half22float2(h1);
    f[0] = a.x; f[1] = a.y; f[2] = b.x; f[3] = b.y;
}

// 64x128: one 64-row A chunk (8KB) vs one 128-row W chunk (16KB)
__device__ __forceinline__ void gemm64(const char* smem, int aoff, int boff, float (&acc)[4][4],
    int wm, int wn, int a_ro, int a_h, int b_ro, int b_h)
{
    const __half* sA = (const __half*)(smem + aoff);
    const __half* sB = (const __half*)(smem + boff);
#pragma unroll
    for (int k16 = 0; k16 < 4; k16++) {
        uint32_t af[4];
        {
            int r = wm * 16 + a_ro;
            int cch = (k16 * 2 + a_h) ^ (r & 7);
            uint32_t ad = (uint32_t)__cvta_generic_to_shared(sA + r * 64 + cch * 8);
            asm volatile("ldmatrix.sync.aligned.m8n8.x4.shared.b16 {%0,%1,%2,%3}, [%4];"
                         : "=r"(af[0]), "=r"(af[1]), "=r"(af[2]), "=r"(af[3]) : "r"(ad));
        }
        uint32_t bf[2][4];
#pragma unroll
        for (int np = 0; np < 2; np++) {
            int r = wn * 32 + np * 16 + b_ro;
            int cch = (k16 * 2 + b_h) ^ (r & 7);
            uint32_t ad = (uint32_t)__cvta_generic_to_shared(sB + r * 64 + cch * 8);
            asm volatile("ldmatrix.sync.aligned.m8n8.x4.shared.b16 {%0,%1,%2,%3}, [%4];"
                         : "=r"(bf[np][0]), "=r"(bf[np][1]), "=r"(bf[np][2]), "=r"(bf[np][3]) : "r"(ad));
        }
#pragma unroll
        for (int nj = 0; nj < 4; nj++) {
            uint32_t b0 = bf[nj >> 1][(nj & 1) * 2 + 0];
            uint32_t b1 = bf[nj >> 1][(nj & 1) * 2 + 1];
            asm volatile("mma.sync.aligned.m16n8k16.row.col.f32.f16.f16.f32 "
                         "{%0,%1,%2,%3}, {%4,%5,%6,%7}, {%8,%9}, {%0,%1,%2,%3};"
                         : "+f"(acc[nj][0]), "+f"(acc[nj][1]), "+f"(acc[nj][2]), "+f"(acc[nj][3])
                         : "r"(af[0]), "r"(af[1]), "r"(af[2]), "r"(af[3]), "r"(b0), "r"(b1));
        }
    }
}

// pointwise for M=64 tile; stage: fp16 (4KB) or fp32 (8KB) at stg
__device__ __forceinline__ void pw64(float (&acc)[4][4], float* c, const float* biasr,
    char* smem, bool xp, int sxr_off, bool fin, int stg, int lane, int wm, int wn)
{
    const int q = lane & 3;
    int r0 = wm * 16 + (lane >> 2);
    float a[4][4], xlo[4], xhi[4];
    if (xp) {
        load4h((const __half*)(smem + sxr_off) + r0 * 4, xlo);
        load4h((const __half*)(smem + sxr_off) + (r0 + 8) * 4, xhi);
    }
#pragma unroll
    for (int nj = 0; nj < 4; nj++) {
        a[nj][0] = acc[nj][0] + biasr[nj * 2];
        a[nj][1] = acc[nj][1] + biasr[nj * 2 + 1];
        a[nj][2] = acc[nj][2] + biasr[nj * 2];
        a[nj][3] = acc[nj][3] + biasr[nj * 2 + 1];
        if (xp) {
            int cl = wn * 32 + nj * 8 + q * 2;
            float w0[4], w1[4];
            load4h((const __half*)(smem + SXW_OFF) + cl * 4, w0);
            load4h((const __half*)(smem + SXW_OFF) + cl * 4 + 4, w1);
            a[nj][0] += xlo[0]*w0[0] + xlo[1]*w0[1] + xlo[2]*w0[2] + xlo[3]*w0[3];
            a[nj][1] += xlo[0]*w1[0] + xlo[1]*w1[1] + xlo[2]*w1[2] + xlo[3]*w1[3];
            a[nj][2] += xhi[0]*w0[0] + xhi[1]*w0[1] + xhi[2]*w0[2] + xhi[3]*w0[3];
            a[nj][3] += xhi[0]*w1[0] + xhi[1]*w1[1] + xhi[2]*w1[2] + xhi[3]*w1[3];
        }
    }
#pragma unroll
    for (int us = 0; us < 2; us++)
#pragma unroll
        for (int ru = 0; ru < 2; ru++) {
            float gi = a[us*2][ru*2], gf = a[us*2][ru*2+1];
            float gg = a[us*2+1][ru*2], go = a[us*2+1][ru*2+1];
            int ci = us * 2 + ru;
            float iv = siga_(gi), fv = siga_(gf), gv = tanha_(gg), ov = siga_(go);
            float cn = fv * c[ci] + iv * gv;
            c[ci] = cn;
            float h = ov * tanha_(cn);
            int row = r0 + ru * 8;
            int jl = wn * 8 + q + us * 4;
            if (fin) ((float*)(smem + stg))[row * 32 + jl] = h;
            else     ((__half*)(smem + stg))[row * 32 + jl] = __float2half(h);
        }
}

// stage (64 rows x 32 cols fp16) -> swizzled global tile slice; tid<256
__device__ __forceinline__ void gran64(char* smem, int stg, char* gdst, int tid, int rank) {
    if (tid < 256) {
        int row = tid >> 2, gg2 = tid & 3;
        uint4 v = *(uint4*)(smem + stg + row * 64 + gg2 * 16);
        int kcc = rank >> 1, g2 = ((rank & 1) << 2) | gg2;
        *(uint4*)(gdst + (size_t)kcc * CHB + row * 128 + ((g2 ^ (row & 7)) << 4)) = v;
    }
}

__global__ void __cluster_dims__(CL, 1, 1) __launch_bounds__(THREADS, 1)
k_lstm(const float* __restrict__ x)
{
    extern __shared__ __align__(1024) char smem[];
    uint32_t sb = smem_u32(smem);
    const int tid = threadIdx.x, lane = tid & 31, warp = tid >> 5;
    const int wm = warp & 3, wn = warp >> 2;
    const int rank = blockIdx.x, cid = blockIdx.y;
    const int s0 = cid * 2, s1 = cid * 2 + 1;
    const int q = lane & 3;
    const int lg = lane >> 3, lr = lane & 7;
    const int a_ro = lr + ((lg & 1) << 3), a_h = lg >> 1;
    const int b_ro = lr + ((lg >> 1) << 3), b_h = lg & 1;
    const uint32_t MB = sb + SMB_OFF;
    const uint32_t mbW = MB + 96;

    if (tid == 0) {
#pragma unroll
        for (int i = 0; i < 12; i++) mbar_init(MB + i * 8, 1);
        mbar_init(mbW, 1);
    }
    __syncthreads();

    int uc[12];
#pragma unroll
    for (int i = 0; i < 12; i++) uc[i] = 0;
    float c0[4] = {0,0,0,0}, c1[4] = {0,0,0,0};
    float biasr[8];

    auto h1t = [&](int t, int sl) { return (char*)g_h1seq + ((size_t)t * 32 + sl) * TILEB; };
    auto h2t = [&](int t, int sl) { return (char*)((t & 1) ? g_h2b : g_h2a) + (size_t)sl * TILEB; };
    auto zt  = [&](int sl) { return (const char*)g_zero + (size_t)sl * TILEB; };

    // ---- phase A setup ----
    if (tid == 0) {
        bulk_in(sb + SW_OFF, (char*)g_W0 + (size_t)rank * 65536, 65536, mbW);
#pragma unroll
        for (int p = 0; p < 4; p++)
            bulk_in(sb + RING_OFF + (2 + p) * CHB, zt(s0) + p * CHB, CHB, MB + (2 + p) * 8);
    }
    if (tid < 128)
        *(uint2*)((__half*)(smem + SXW_OFF) + tid * 4) = *(const uint2*)&g_Wx0h[(rank * 128 + tid) * 4];
#pragma unroll
    for (int nj = 0; nj < 4; nj++) {
        biasr[nj * 2 + 0] = g_b0[rank * 128 + wn * 32 + nj * 8 + q * 2 + 0];
        biasr[nj * 2 + 1] = g_b0[rank * 128 + wn * 32 + nj * 8 + q * 2 + 1];
    }
    mbar_wait(mbW, 0);
    __syncthreads();
    clsync();

    // ---- phase A: layer 0, dual-tile half-steps ----
#pragma unroll 1
    for (int t = 0; t < T_; t++) {
#pragma unroll
        for (int X = 0; X < 2; X++) {
            const int TS = X * 6;
            const int sl = X ? s1 : s0;
            float* c = X ? c1 : c0;
            if (tid < 64) {
                float4 v = *(const float4*)(x + ((size_t)(sl * 64 + tid) * T_ + t) * D_);
                __half2 p0 = __floats2half2_rn(v.x, v.y), p1 = __floats2half2_rn(v.z, v.w);
                uint2 u; u.x = *reinterpret_cast<uint32_t*>(&p0); u.y = *reinterpret_cast<uint32_t*>(&p1);
                *(uint2*)(smem + SXR_OFF + X * 512 + tid * 8) = u;
            }
            float acc[4][4];
#pragma unroll
            for (int nj = 0; nj < 4; nj++)
#pragma unroll
                for (int e = 0; e < 4; e++) acc[nj][e] = 0.f;
#pragma unroll
            for (int kc = 0; kc < 4; kc++) {
                int si = TS + 2 + kc;
                mbar_wait(MB + si * 8, uc[si] & 1); uc[si]++;
                gemm64(smem, RING_OFF + si * CHB, SW_OFF + kc * WCH, acc, wm, wn, a_ro, a_h, b_ro, b_h);
            }
            __syncthreads();
            if (tid == 0) {
                if (X == 0) {
                    const char* src = (t == 0) ? zt(s1) : h1t(t - 1, s1);
#pragma unroll
                    for (int p = 0; p < 4; p++)
                        bulk_in(sb + RING_OFF + (8 + p) * CHB, src + p * CHB, CHB, MB + (8 + p) * 8);
                } else if (t < T_ - 1) {
                    const char* src = h1t(t, s0);
#pragma unroll
                    for (int p = 0; p < 4; p++)
                        bulk_in(sb + RING_OFF + (2 + p) * CHB, src + p * CHB, CHB, MB + (2 + p) * 8);
                }
            }
            pw64(acc, c, biasr, smem, true, SXR_OFF + X * 512, false, RING_OFF + (TS + 2) * CHB,
                 lane, wm, wn);
            __syncthreads();
            gran64(smem, RING_OFF + (TS + 2) * CHB, h1t(t, sl), tid, rank);
            asm volatile("fence.proxy.async;" ::: "memory");
            clsync();
        }
    }

    // ---- phase boundary ----
    if (tid == 0) {
        bulk_in(sb + SW_OFF, (char*)g_W1 + (size_t)rank * 131072, 131072, mbW);
        bulk_in(sb + RING_OFF + 0 * CHB, h1t(0, s0) + 0 * CHB, CHB, MB + 0);
        bulk_in(sb + RING_OFF + 1 * CHB, h1t(0, s0) + 1 * CHB, CHB, MB + 8);
#pragma unroll
        for (int p = 0; p < 4; p++)
            bulk_in(sb + RING_OFF + (2 + p) * CHB, zt(s0) + p * CHB, CHB, MB + (2 + p) * 8);
    }
#pragma unroll
    for (int nj = 0; nj < 4; nj++) {
        biasr[nj * 2 + 0] = g_b1[rank * 128 + wn * 32 + nj * 8 + q * 2 + 0];
        biasr[nj * 2 + 1] = g_b1[rank * 128 + wn * 32 + nj * 8 + q * 2 + 1];
    }
#pragma unroll
    for (int i = 0; i < 4; i++) { c0[i] = 0.f; c1[i] = 0.f; }
    mbar_wait(mbW, 1);
    __syncthreads();

    // ---- phase B: layer 1, dual-tile half-steps ----
#pragma unroll 1
    for (int t = 0; t < T_; t++) {
#pragma unroll
        for (int X = 0; X < 2; X++) {
            const int TS = X * 6;
            const int sl = X ? s1 : s0;
            float* c = X ? c1 : c0;
            const bool fin = (t == T_ - 1);
            const char* xsrc = h1t(t, sl);
            float acc[4][4];
#pragma unroll
            for (int nj = 0; nj < 4; nj++)
#pragma unroll
                for (int e = 0; e < 4; e++) acc[nj][e] = 0.f;
            mbar_wait(MB + (TS + 0) * 8, uc[TS + 0] & 1); uc[TS + 0]++;
            gemm64(smem, RING_OFF + (TS + 0) * CHB, SW_OFF + 0 * WCH, acc, wm, wn, a_ro, a_h, b_ro, b_h);
            __syncthreads();
            if (tid == 0) bulk_in(sb + RING_OFF + (TS + 0) * CHB, xsrc + 2 * CHB, CHB, MB + (TS + 0) * 8);
            mbar_wait(MB + (TS + 1) * 8, uc[TS + 1] & 1); uc[TS + 1]++;
            gemm64(smem, RING_OFF + (TS + 1) * CHB, SW_OFF + 1 * WCH, acc, wm, wn, a_ro, a_h, b_ro, b_h);
            __syncthreads();
            if (tid == 0) bulk_in(sb + RING_OFF + (TS + 1) * CHB, xsrc + 3 * CHB, CHB, MB + (TS + 1) * 8);
            mbar_wait(MB + (TS + 0) * 8, uc[TS + 0] & 1); uc[TS + 0]++;
            gemm64(smem, RING_OFF + (TS + 0) * CHB, SW_OFF + 2 * WCH, acc, wm, wn, a_ro, a_h, b_ro, b_h);
            mbar_wait(MB + (TS + 1) * 8, uc[TS + 1] & 1); uc[TS + 1]++;
            gemm64(smem, RING_OFF + (TS + 1) * CHB, SW_OFF + 3 * WCH, acc, wm, wn, a_ro, a_h, b_ro, b_h);
#pragma unroll
            for (int p = 0; p < 4; p++) {
                int si = TS + 2 + p;
                mbar_wait(MB + si * 8, uc[si] & 1); uc[si]++;
                gemm64(smem, RING_OFF + si * CHB, SW_OFF + (4 + p) * WCH, acc, wm, wn, a_ro, a_h, b_ro, b_h);
            }
            __syncthreads();
            if (tid == 0) {
                if (X == 0) {
                    const char* ox = h1t(t, s1);
                    const char* oh = (t == 0) ? zt(s1) : h2t(t - 1, s1);
                    bulk_in(sb + RING_OFF + 6 * CHB, ox + 0 * CHB, CHB, MB + 48);
                    bulk_in(sb + RING_OFF + 7 * CHB, ox + 1 * CHB, CHB, MB + 56);
#pragma unroll
                    for (int p = 0; p < 4; p++)
                        bulk_in(sb + RING_OFF + (8 + p) * CHB, oh + p * CHB, CHB, MB + (8 + p) * 8);
                } else if (t < T_ - 1) {
                    const char* ox = h1t(t + 1, s0);
                    const char* oh = h2t(t, s0);
                    bulk_in(sb + RING_OFF + 0 * CHB, ox + 0 * CHB, CHB, MB + 0);
                    bulk_in(sb + RING_OFF + 1 * CHB, ox + 1 * CHB, CHB, MB + 8);
#pragma unroll
                    for (int p = 0; p < 4; p++)
                        bulk_in(sb + RING_OFF + (2 + p) * CHB, oh + p * CHB, CHB, MB + (2 + p) * 8);
                }
            }
            pw64(acc, c, biasr, smem, false, 0, fin, RING_OFF + (TS + 2) * CHB, lane, wm, wn);
            __syncthreads();
            if (fin) {
                float* fs = (float*)(smem + RING_OFF + (TS + 2) * CHB);
                float* fd = g_h2f + (size_t)sl * 64 * H_;
#pragma unroll
                for (int p = 0; p < 4; p++) {
                    int idx = tid + p * 512;
                    int row = idx >> 5, cc = idx & 31;
                    fd[(size_t)row * H_ + rank * 32 + cc] = fs[row * 32 + cc];
                }
            } else {
                gran64(smem, RING_OFF + (TS + 2) * CHB, h2t(t, sl), tid, rank);
            }
            asm volatile("fence.proxy.async;" ::: "memory");
            clsync();
        }
    }
}

__global__ void k_fc(const float* __restrict__ Wfc, const float* __restrict__ bfc,
                     float* __restrict__ out) {
    int b = blockIdx.x;
    int o = threadIdx.y;
    int lane = threadIdx.x;
    const float* hr = g_h2f + (size_t)b * H_;
    const float* wr = Wfc + (size_t)o * H_;
    float s = 0.f;
    for (int j = lane; j < H_; j += 32) s += hr[j] * wr[j];
#pragma unroll
    for (int off = 16; off; off >>= 1) s += __shfl_xor_sync(0xffffffffu, s, off);
    if (lane == 0) out[b * 6 + o] = s + bfc[o];
}

extern "C" void kernel_launch(void* const* d_in, const int* in_sizes, int n_in,
                              void* d_out, int out_size) {
    const float* x     = (const float*)d_in[0];
    const float* W_ih0 = (const float*)d_in[1];
    const float* W_hh0 = (const float*)d_in[2];
    const float* b_ih0 = (const float*)d_in[3];
    const float* b_hh0 = (const float*)d_in[4];
    const float* W_ih1 = (const float*)d_in[5];
    const float* W_hh1 = (const float*)d_in[6];
    const float* b_ih1 = (const float*)d_in[7];
    const float* b_hh1 = (const float*)d_in[8];
    const float* W_fc  = (const float*)d_in[9];
    const float* b_fc  = (const float*)d_in[10];

    cudaFuncSetAttribute(k_lstm, cudaFuncAttributeMaxDynamicSharedMemorySize, SMEM_TOTAL);

    k_init<<<256, 256>>>();
    k_pack0<<<512, 256>>>(W_ih0, W_hh0, b_ih0, b_hh0);
    k_pack1<<<1024, 256>>>(W_ih1, W_hh1, b_ih1, b_hh1);

    k_lstm<<<dim3(CL, 16), THREADS, SMEM_TOTAL>>>(x);

    k_fc<<<B_, dim3(32, 6)>>>(W_fc, b_fc, (float*)d_out);
}

// round 15
// speedup vs baseline: 1.3226x; 1.3226x over previous
#include <cuda_runtime.h>
#include <cuda_fp16.h>
#include <cstdint>
#include <cstddef>

#define B_ 2048
#define T_ 200
#define D_ 4
#define H_ 256
#define G_ 1024
#define CL 8
#define THREADS 512
#define CH 16384
#define TILE 65536

// smem layout
#define SW_OFF    0                   // W: phase A 5 chunks (80KB), phase B 8 chunks (128KB)
#define STGA_OFF  81920               // phase A staging (within unused W region)
#define RING_OFF  131072              // 6 slots * 16KB
#define STGB_OFF  (RING_OFF + 4*CH)   // phase B staging = slot 4
#define SMB_OFF   (RING_OFF + 6*CH)   // 6 slot mbars + W mbar
#define SMEM_TOTAL (SMB_OFF + 64)

__device__ __align__(128) __half g_W0[G_ * 320];   // [rank][5 chunks] swizzled
__device__ __align__(128) float  g_b0[G_];
__device__ __align__(128) __half g_W1[G_ * 512];   // [rank][8 chunks]
__device__ __align__(128) float  g_b1[G_];
__device__ __align__(128) __half g_x16[(size_t)T_ * B_ * 64];  // [(t*16+ms)] 16KB images
__device__ __align__(128) __half g_zero[B_ * H_];
__device__ __align__(128) __half g_h1seq[(size_t)T_ * B_ * H_];
__device__ __align__(128) __half g_h2a[B_ * H_];
__device__ __align__(128) __half g_h2b[B_ * H_];
__device__ __align__(128) float  g_h2f[B_ * H_];

__global__ void k_init() {
    int s = gridDim.x * blockDim.x;
    for (int i = blockIdx.x * blockDim.x + threadIdx.x; i < B_ * H_; i += s)
        g_zero[i] = __float2half(0.f);
}
__device__ __forceinline__ size_t swoff(int r, int k) {
    int kc = k >> 6, cc = k & 63, g = cc >> 3, e = cc & 7;
    return (size_t)kc * CH + r * 128 + ((g ^ (r & 7)) << 4) + e * 2;
}
__device__ __forceinline__ int col2row(int n) {
    int c = n & 31;
    int j = (n >> 5) * 8 + ((c >> 4) << 2) + ((c >> 1) & 3);
    int blk = (c >> 3) & 1, e = c & 1;
    int g = blk ? (e ? 3 : 2) : (e ? 1 : 0);
    return g * H_ + j;
}
__global__ void k_packx(const float* __restrict__ x) {
    int s = gridDim.x * blockDim.x;
    const int N = T_ * B_ * 64;
    for (int i = blockIdx.x * blockDim.x + threadIdx.x; i < N; i += s) {
        int k = i & 63, b = (i >> 6) & (B_ - 1), t = i >> 17;
        float v = (k < D_) ? x[((size_t)b * T_ + t) * D_ + k] : 0.f;
        int ms = b >> 7, r = b & 127;
        *(__half*)((char*)g_x16 + (size_t)(t * 16 + ms) * CH + swoff(r, k)) = __float2half(v);
    }
}
__global__ void k_pack0(const float* __restrict__ Wi, const float* __restrict__ Wh,
                        const float* __restrict__ bi, const float* __restrict__ bh) {
    int s = gridDim.x * blockDim.x;
    const int N = G_ * 320;
    for (int i = blockIdx.x * blockDim.x + threadIdx.x; i < N; i += s) {
        int n = i / 320, k = i % 320;
        int orow = col2row(n);
        int rank = n >> 7, r = n & 127;
        float v = (k < 64) ? ((k < D_) ? Wi[orow * D_ + k] : 0.f) : Wh[orow * H_ + (k - 64)];
        *(__half*)((char*)g_W0 + (size_t)rank * 81920 + swoff(r, k)) = __float2half(v);
        if (k == 0) g_b0[n] = bi[orow] + bh[orow];
    }
}
__global__ void k_pack1(const float* __restrict__ Wi, const float* __restrict__ Wh,
                        const float* __restrict__ bi, const float* __restrict__ bh) {
    int s = gridDim.x * blockDim.x;
    for (int i = blockIdx.x * blockDim.x + threadIdx.x; i < G_ * 512; i += s) {
        int n = i >> 9, k = i & 511;
        int orow = col2row(n);
        int rank = n >> 7, r = n & 127;
        float v = (k < H_) ? Wi[orow * H_ + k] : Wh[orow * H_ + (k - H_)];
        *(__half*)((char*)g_W1 + (size_t)rank * 131072 + swoff(r, k)) = __float2half(v);
        if (k == 0) g_b1[n] = bi[orow] + bh[orow];
    }
}

__device__ __forceinline__ uint32_t smem_u32(const void* p) {
    uint32_t a;
    asm("{ .reg .u64 t; cvta.to.shared.u64 t, %1; cvt.u32.u64 %0, t; }" : "=r"(a) : "l"(p));
    return a;
}
__device__ __forceinline__ void cl_arrive() { asm volatile("barrier.cluster.arrive.aligned;" ::: "memory"); }
__device__ __forceinline__ void cl_wait()   { asm volatile("barrier.cluster.wait.aligned;" ::: "memory"); }
__device__ __forceinline__ float tanha_(float x) {
    float r; asm("tanh.approx.f32 %0, %1;" : "=f"(r) : "f"(x));
    return r;
}
__device__ __forceinline__ float siga_(float x) { return __fmaf_rn(tanha_(0.5f * x), 0.5f, 0.5f); }
__device__ __forceinline__ void mbar_init(uint32_t m, uint32_t c) {
    asm volatile("mbarrier.init.shared.b64 [%0], %1;" :: "r"(m), "r"(c) : "memory");
}
__device__ __forceinline__ void bulk_in(uint32_t sdst, const void* g, uint32_t bytes, uint32_t mb) {
    asm volatile("mbarrier.arrive.expect_tx.shared.b64 _, [%0], %1;" :: "r"(mb), "r"(bytes) : "memory");
    asm volatile("cp.async.bulk.shared::cluster.global.mbarrier::complete_tx::bytes [%0], [%1], %2, [%3];"
                 :: "r"(sdst), "l"(g), "r"(bytes), "r"(mb) : "memory");
}
__device__ __forceinline__ void mbar_wait(uint32_t m, uint32_t par) {
    uint32_t done;
    asm volatile("{.reg .pred p; mbarrier.try_wait.parity.acquire.cta.shared::cta.b64 p, [%1], %2; selp.b32 %0,1,0,p;}"
                 : "=r"(done) : "r"(m), "r"(par) : "memory");
    if (!done) {
        asm volatile("{.reg .pred P1;\nWL_%=:\n"
                     "mbarrier.try_wait.parity.acquire.cta.shared::cta.b64 P1, [%0], %1, 0x989680;\n"
                     "@P1 bra.uni WD_%=;\nbra.uni WL_%=;\nWD_%=:\n}"
                     :: "r"(m), "r"(par) : "memory");
    }
}

// M=128 x N=128 gemm on one 16KB A chunk vs one 16KB W chunk
__device__ __forceinline__ void gemm_chunk(
    const char* smem, int aoff, int boff, float (&acc)[2][4][4],
    int wm, int wn, int a_ro, int a_h, int b_ro, int b_h)
{
    const __half* sA = (const __half*)(smem + aoff);
    const __half* sB = (const __half*)(smem + boff);
#pragma unroll
    for (int k16 = 0; k16 < 4; k16++) {
        uint32_t afr[2][4];
#pragma unroll
        for (int mi = 0; mi < 2; mi++) {
            int r = wm * 32 + mi * 16 + a_ro;
            int cch = (k16 * 2 + a_h) ^ (r & 7);
            uint32_t ad = (uint32_t)__cvta_generic_to_shared(sA + r * 64 + cch * 8);
            asm volatile("ldmatrix.sync.aligned.m8n8.x4.shared.b16 {%0,%1,%2,%3}, [%4];"
                         : "=r"(afr[mi][0]), "=r"(afr[mi][1]), "=r"(afr[mi][2]), "=r"(afr[mi][3])
                         : "r"(ad));
        }
        uint32_t bfr[2][4];
#pragma unroll
        for (int np = 0; np < 2; np++) {
            int r = wn * 32 + np * 16 + b_ro;
            int cch = (k16 * 2 + b_h) ^ (r & 7);
            uint32_t ad = (uint32_t)__cvta_generic_to_shared(sB + r * 64 + cch * 8);
            asm volatile("ldmatrix.sync.aligned.m8n8.x4.shared.b16 {%0,%1,%2,%3}, [%4];"
                         : "=r"(bfr[np][0]), "=r"(bfr[np][1]), "=r"(bfr[np][2]), "=r"(bfr[np][3])
                         : "r"(ad));
        }
#pragma unroll
        for (int mi = 0; mi < 2; mi++)
#pragma unroll
            for (int nj = 0; nj < 4; nj++) {
                uint32_t b0 = bfr[nj >> 1][(nj & 1) * 2 + 0];
                uint32_t b1 = bfr[nj >> 1][(nj & 1) * 2 + 1];
                asm volatile("mma.sync.aligned.m16n8k16.row.col.f32.f16.f16.f32 "
                             "{%0,%1,%2,%3}, {%4,%5,%6,%7}, {%8,%9}, {%0,%1,%2,%3};"
                             : "+f"(acc[mi][nj][0]), "+f"(acc[mi][nj][1]),
                               "+f"(acc[mi][nj][2]), "+f"(acc[mi][nj][3])
                             : "r"(afr[mi][0]), "r"(afr[mi][1]), "r"(afr[mi][2]), "r"(afr[mi][3]),
                               "r"(b0), "r"(b1));
            }
    }
}

// pointwise: gates -> c,h; stage fp16 (or fp32 if FIN) at stg
template<bool FIN>
__device__ __forceinline__ void pw(float (&acc)[2][4][4], float* c, const float* biasr,
                                   char* smem, int stg, int lane, int wm, int wn)
{
    const int q = lane & 3;
    __half* hs = (__half*)(smem + stg);
    float*  fs = (float*)(smem + stg);
#pragma unroll
    for (int mi = 0; mi < 2; mi++) {
        int r0 = wm * 32 + mi * 16 + (lane >> 2);
#pragma unroll
        for (int us = 0; us < 2; us++)
#pragma unroll
            for (int ru = 0; ru < 2; ru++) {
                float gi = acc[mi][us*2+0][ru*2+0] + biasr[us*4+0];
                float gf = acc[mi][us*2+0][ru*2+1] + biasr[us*4+1];
                float gg = acc[mi][us*2+1][ru*2+0] + biasr[us*4+2];
                float go = acc[mi][us*2+1][ru*2+1] + biasr[us*4+3];
                int ci = mi * 4 + us * 2 + ru;
                float iv = siga_(gi), fv = siga_(gf), gv = tanha_(gg), ov = siga_(go);
                float cn = fv * c[ci] + iv * gv;
                c[ci] = cn;
                float h = ov * tanha_(cn);
                int row = r0 + ru * 8;
                int jl = wn * 8 + q + us * 4;
                if (FIN) fs[row * 32 + jl] = h;
                else     hs[row * 32 + jl] = __float2half(h);
            }
    }
}

__device__ __forceinline__ void gran(char* smem, int stg, char* gdst, int tid, int rank) {
    int row = tid >> 2, gg2 = tid & 3;
    uint4 v = *(uint4*)(smem + stg + row * 64 + gg2 * 16);
    int kcc = rank >> 1, g2 = ((rank & 1) << 2) | gg2;
    *(uint4*)(gdst + (size_t)kcc * CH + row * 128 + ((g2 ^ (row & 7)) << 4)) = v;
}

__global__ void __cluster_dims__(CL, 1, 1) __launch_bounds__(THREADS, 1)
k_lstm()
{
    extern __shared__ __align__(1024) char smem[];
    uint32_t sb = smem_u32(smem);
    const int tid = threadIdx.x, lane = tid & 31, warp = tid >> 5;
    const int wm = warp & 3, wn = warp >> 2;
    const int rank = blockIdx.x, ms = blockIdx.y;
    const int mbase = ms * 128, nbase = rank * 128;
    const int q = lane & 3;
    const int lg = lane >> 3, lr = lane & 7;
    const int a_ro = lr + ((lg & 1) << 3), a_h = lg >> 1;
    const int b_ro = lr + ((lg >> 1) << 3), b_h = lg & 1;
    const uint32_t MB = sb + SMB_OFF;
    const uint32_t mbW = MB + 48;

    if (tid == 0) {
#pragma unroll
        for (int i = 0; i < 6; i++) mbar_init(MB + i * 8, 1);
        mbar_init(mbW, 1);
    }
    __syncthreads();

    int uc[6] = {0, 0, 0, 0, 0, 0};
    float biasr[8], c[8];
    auto h1t = [&](int t) { return (char*)g_h1seq + ((size_t)t * 16 + ms) * TILE; };
    auto h2t = [&](int t) { return (char*)((t & 1) ? g_h2b : g_h2a) + (size_t)ms * TILE; };
    const char* zt = (const char*)g_zero + (size_t)ms * TILE;
    auto xt = [&](int t) { return (const char*)g_x16 + (size_t)(t * 16 + ms) * CH; };

    // ---- phase A setup: W0 (5 chunks) + x(0) into slot 4 ----
    if (tid == 0) {
        bulk_in(sb + SW_OFF, (char*)g_W0 + (size_t)rank * 81920, 81920, mbW);
        bulk_in(sb + RING_OFF + 4 * CH, xt(0), CH, MB + 32);
    }
#pragma unroll
    for (int nj = 0; nj < 4; nj++) {
        biasr[nj * 2 + 0] = g_b0[nbase + wn * 32 + nj * 8 + q * 2 + 0];
        biasr[nj * 2 + 1] = g_b0[nbase + wn * 32 + nj * 8 + q * 2 + 1];
    }
#pragma unroll
    for (int i = 0; i < 8; i++) c[i] = 0.f;
    mbar_wait(mbW, 0);
    __syncthreads();
    cl_arrive();

    // ---- phase A: layer 0, K=320 ----
#pragma unroll 1
    for (int t = 0; t < T_; t++) {
        float acc[2][4][4];
#pragma unroll
        for (int mi = 0; mi < 2; mi++)
#pragma unroll
            for (int nj = 0; nj < 4; nj++)
#pragma unroll
                for (int e = 0; e < 4; e++) acc[mi][nj][e] = 0.f;
        // independent x chunk before the cluster wait
        int sx = 4 + (t & 1);
        mbar_wait(MB + sx * 8, uc[sx] & 1); uc[sx]++;
        gemm_chunk(smem, RING_OFF + sx * CH, SW_OFF + 0, acc, wm, wn, a_ro, a_h, b_ro, b_h);
        cl_wait();
        __syncthreads();
        if (tid == 0) {
            const char* hs = (t == 0) ? zt : h1t(t - 1);
#pragma unroll
            for (int p = 0; p < 4; p++)
                bulk_in(sb + RING_OFF + p * CH, hs + p * CH, CH, MB + p * 8);
        }
#pragma unroll
        for (int kc = 0; kc < 4; kc++) {
            mbar_wait(MB + kc * 8, uc[kc] & 1); uc[kc]++;
            gemm_chunk(smem, RING_OFF + kc * CH, SW_OFF + (1 + kc) * CH, acc,
                       wm, wn, a_ro, a_h, b_ro, b_h);
        }
        __syncthreads();
        if (tid == 0 && t + 1 < T_)
            bulk_in(sb + RING_OFF + (4 + ((t + 1) & 1)) * CH, xt(t + 1), CH,
                    MB + (4 + ((t + 1) & 1)) * 8);
        pw<false>(acc, c, biasr, smem, STGA_OFF, lane, wm, wn);
        __syncthreads();
        gran(smem, STGA_OFF, h1t(t), tid, rank);
        asm volatile("fence.proxy.async;" ::: "memory");
        cl_arrive();
    }

    // ---- phase boundary ----
    cl_wait();
    __syncthreads();
    if (tid == 0) {
        bulk_in(sb + SW_OFF, (char*)g_W1 + (size_t)rank * 131072, 131072, mbW);
#pragma unroll
        for (int p = 0; p < 4; p++)
            bulk_in(sb + RING_OFF + p * CH, h1t(0) + p * CH, CH, MB + p * 8);
    }
#pragma unroll
    for (int nj = 0; nj < 4; nj++) {
        biasr[nj * 2 + 0] = g_b1[nbase + wn * 32 + nj * 8 + q * 2 + 0];
        biasr[nj * 2 + 1] = g_b1[nbase + wn * 32 + nj * 8 + q * 2 + 1];
    }
#pragma unroll
    for (int i = 0; i < 8; i++) c[i] = 0.f;
    mbar_wait(mbW, 1);
    __syncthreads();
    cl_arrive();

    // ---- phase B: layer 1, K=512 ----
#pragma unroll 1
    for (int t = 0; t < T_; t++) {
        bool fin = (t == T_ - 1);
        float acc[2][4][4];
#pragma unroll
        for (int mi = 0; mi < 2; mi++)
#pragma unroll
            for (int nj = 0; nj < 4; nj++)
#pragma unroll
                for (int e = 0; e < 4; e++) acc[mi][nj][e] = 0.f;
        // 4 independent x chunks before the cluster wait
#pragma unroll
        for (int kc = 0; kc < 4; kc++) {
            mbar_wait(MB + kc * 8, uc[kc] & 1); uc[kc]++;
            gemm_chunk(smem, RING_OFF + kc * CH, SW_OFF + kc * CH, acc,
                       wm, wn, a_ro, a_h, b_ro, b_h);
        }
        cl_wait();
        __syncthreads();
        if (tid == 0) {
            const char* hs = (t == 0) ? zt : h2t(t - 1);
            bulk_in(sb + RING_OFF + 4 * CH, hs + 0 * CH, CH, MB + 32);
            bulk_in(sb + RING_OFF + 5 * CH, hs + 1 * CH, CH, MB + 40);
            bulk_in(sb + RING_OFF + 2 * CH, hs + 2 * CH, CH, MB + 16);
            bulk_in(sb + RING_OFF + 3 * CH, hs + 3 * CH, CH, MB + 24);
        }
        {   // h chunks: W chunks 4..7 on slots 4,5,2,3
            mbar_wait(MB + 32, uc[4] & 1); uc[4]++;
            gemm_chunk(smem, RING_OFF + 4 * CH, SW_OFF + 4 * CH, acc, wm, wn, a_ro, a_h, b_ro, b_h);
            mbar_wait(MB + 40, uc[5] & 1); uc[5]++;
            gemm_chunk(smem, RING_OFF + 5 * CH, SW_OFF + 5 * CH, acc, wm, wn, a_ro, a_h, b_ro, b_h);
            mbar_wait(MB + 16, uc[2] & 1); uc[2]++;
            gemm_chunk(smem, RING_OFF + 2 * CH, SW_OFF + 6 * CH, acc, wm, wn, a_ro, a_h, b_ro, b_h);
            mbar_wait(MB + 24, uc[3] & 1); uc[3]++;
            gemm_chunk(smem, RING_OFF + 3 * CH, SW_OFF + 7 * CH, acc, wm, wn, a_ro, a_h, b_ro, b_h);
        }
        __syncthreads();
        if (tid == 0 && t + 1 < T_) {
#pragma unroll
            for (int p = 0; p < 4; p++)
                bulk_in(sb + RING_OFF + p * CH, h1t(t + 1) + p * CH, CH, MB + p * 8);
        }
        if (fin) {
            pw<true>(acc, c, biasr, smem, STGB_OFF, lane, wm, wn);
            __syncthreads();
            float* fd = g_h2f + (size_t)mbase * H_;
#pragma unroll
            for (int p = 0; p < 8; p++) {
                int row = p * 16 + (tid >> 5);
                int cc = tid & 31;
                fd[(size_t)row * H_ + rank * 32 + cc] =
                    *(float*)(smem + STGB_OFF + (row * 32 + cc) * 4);
            }
        } else {
            pw<false>(acc, c, biasr, smem, STGB_OFF, lane, wm, wn);
            __syncthreads();
            gran(smem, STGB_OFF, h2t(t), tid, rank);
        }
        asm volatile("fence.proxy.async;" ::: "memory");
        cl_arrive();
    }
    cl_wait();   // balance the final arrive
}

__global__ void k_fc(const float* __restrict__ Wfc, const float* __restrict__ bfc,
                     float* __restrict__ out) {
    int b = blockIdx.x;
    int o = threadIdx.y;
    int lane = threadIdx.x;
    const float* hr = g_h2f + (size_t)b * H_;
    const float* wr = Wfc + (size_t)o * H_;
    float s = 0.f;
    for (int j = lane; j < H_; j += 32) s += hr[j] * wr[j];
#pragma unroll
    for (int off = 16; off; off >>= 1) s += __shfl_xor_sync(0xffffffffu, s, off);
    if (lane == 0) out[b * 6 + o] = s + bfc[o];
}

extern "C" void kernel_launch(void* const* d_in, const int* in_sizes, int n_in,
                              void* d_out, int out_size) {
    const float* x     = (const float*)d_in[0];
    const float* W_ih0 = (const float*)d_in[1];
    const float* W_hh0 = (const float*)d_in[2];
    const float* b_ih0 = (const float*)d_in[3];
    const float* b_hh0 = (const float*)d_in[4];
    const float* W_ih1 = (const float*)d_in[5];
    const float* W_hh1 = (const float*)d_in[6];
    const float* b_ih1 = (const float*)d_in[7];
    const float* b_hh1 = (const float*)d_in[8];
    const float* W_fc  = (const float*)d_in[9];
    const float* b_fc  = (const float*)d_in[10];

    cudaFuncSetAttribute(k_lstm, cudaFuncAttributeMaxDynamicSharedMemorySize, SMEM_TOTAL);

    k_init<<<256, 256>>>();
    k_packx<<<4096, 256>>>(x);
    k_pack0<<<640, 256>>>(W_ih0, W_hh0, b_ih0, b_hh0);
    k_pack1<<<1024, 256>>>(W_ih1, W_hh1, b_ih1, b_hh1);

    k_lstm<<<dim3(CL, 16), THREADS, SMEM_TOTAL>>>();

    k_fc<<<B_, dim3(32, 6)>>>(W_fc, b_fc, (float*)d_out);
}

// round 16
// speedup vs baseline: 1.7385x; 1.3144x over previous
#include <cuda_runtime.h>
#include <cuda_fp16.h>
#include <cstdint>
#include <cstddef>

#define B_ 2048
#define T_ 200
#define D_ 4
#define H_ 256
#define G_ 1024
#define THREADS 512
#define CH 16384
#define TILE 65536

// smem layout
#define SW_OFF    0                   // W: phase A 5 chunks (80KB), phase B 8 chunks (128KB)
#define STGA_OFF  81920               // phase A staging (inside unused W region)
#define RING_OFF  131072              // 6 slots * 16KB
#define STGB_OFF  (RING_OFF + 4*CH)   // phase B staging = slot 4 region
#define SMB_OFF   (RING_OFF + 6*CH)   // 6 slot mbars + W mbar
#define SMEM_TOTAL (SMB_OFF + 64)

__device__ __align__(128) __half g_W0[G_ * 320];
__device__ __align__(128) float  g_b0[G_];
__device__ __align__(128) __half g_W1[G_ * 512];
__device__ __align__(128) float  g_b1[G_];
__device__ __align__(128) __half g_x16[(size_t)T_ * B_ * 64];
__device__ __align__(128) __half g_zero[B_ * H_];
__device__ __align__(128) __half g_h1seq[(size_t)T_ * B_ * H_];
__device__ __align__(128) __half g_h2a[B_ * H_];
__device__ __align__(128) __half g_h2b[B_ * H_];
__device__ __align__(128) float  g_h2f[B_ * H_];
__device__ int g_f1[16 * 8];   // layer0 steps completed per (ms, rank)
__device__ int g_f2[16 * 8];   // layer1 steps completed
__device__ int g_fr[16 * 8];   // layer1 h-read (TMA) steps completed

__global__ void k_init() {
    int s = gridDim.x * blockDim.x;
    int i0 = blockIdx.x * blockDim.x + threadIdx.x;
    for (int i = i0; i < B_ * H_; i += s) g_zero[i] = __float2half(0.f);
    if (i0 < 16 * 8) { g_f1[i0] = 0; g_f2[i0] = 0; g_fr[i0] = 0; }
}
__device__ __forceinline__ size_t swoff(int r, int k) {
    int kc = k >> 6, cc = k & 63, g = cc >> 3, e = cc & 7;
    return (size_t)kc * CH + r * 128 + ((g ^ (r & 7)) << 4) + e * 2;
}
__device__ __forceinline__ int col2row(int n) {
    int c = n & 31;
    int j = (n >> 5) * 8 + ((c >> 4) << 2) + ((c >> 1) & 3);
    int blk = (c >> 3) & 1, e = c & 1;
    int g = blk ? (e ? 3 : 2) : (e ? 1 : 0);
    return g * H_ + j;
}
__global__ void k_packx(const float* __restrict__ x) {
    int s = gridDim.x * blockDim.x;
    const int N = T_ * B_ * 64;
    for (int i = blockIdx.x * blockDim.x + threadIdx.x; i < N; i += s) {
        int k = i & 63, b = (i >> 6) & (B_ - 1), t = i >> 17;
        float v = (k < D_) ? x[((size_t)b * T_ + t) * D_ + k] : 0.f;
        int ms = b >> 7, r = b & 127;
        *(__half*)((char*)g_x16 + (size_t)(t * 16 + ms) * CH + swoff(r, k)) = __float2half(v);
    }
}
__global__ void k_pack0(const float* __restrict__ Wi, const float* __restrict__ Wh,
                        const float* __restrict__ bi, const float* __restrict__ bh) {
    int s = gridDim.x * blockDim.x;
    const int N = G_ * 320;
    for (int i = blockIdx.x * blockDim.x + threadIdx.x; i < N; i += s) {
        int n = i / 320, k = i % 320;
        int orow = col2row(n);
        int rank = n >> 7, r = n & 127;
        float v = (k < 64) ? ((k < D_) ? Wi[orow * D_ + k] : 0.f) : Wh[orow * H_ + (k - 64)];
        *(__half*)((char*)g_W0 + (size_t)rank * 81920 + swoff(r, k)) = __float2half(v);
        if (k == 0) g_b0[n] = bi[orow] + bh[orow];
    }
}
__global__ void k_pack1(const float* __restrict__ Wi, const float* __restrict__ Wh,
                        const float* __restrict__ bi, const float* __restrict__ bh) {
    int s = gridDim.x * blockDim.x;
    for (int i = blockIdx.x * blockDim.x + threadIdx.x; i < G_ * 512; i += s) {
        int n = i >> 9, k = i & 511;
        int orow = col2row(n);
        int rank = n >> 7, r = n & 127;
        float v = (k < H_) ? Wi[orow * H_ + k] : Wh[orow * H_ + (k - H_)];
        *(__half*)((char*)g_W1 + (size_t)rank * 131072 + swoff(r, k)) = __float2half(v);
        if (k == 0) g_b1[n] = bi[orow] + bh[orow];
    }
}

__device__ __forceinline__ uint32_t smem_u32(const void* p) {
    uint32_t a;
    asm("{ .reg .u64 t; cvta.to.shared.u64 t, %1; cvt.u32.u64 %0, t; }" : "=r"(a) : "l"(p));
    return a;
}
__device__ __forceinline__ float tanha_(float x) {
    float r; asm("tanh.approx.f32 %0, %1;" : "=f"(r) : "f"(x));
    return r;
}
__device__ __forceinline__ float siga_(float x) { return __fmaf_rn(tanha_(0.5f * x), 0.5f, 0.5f); }
__device__ __forceinline__ void mbar_init(uint32_t m, uint32_t c) {
    asm volatile("mbarrier.init.shared.b64 [%0], %1;" :: "r"(m), "r"(c) : "memory");
}
__device__ __forceinline__ void bulk_in(uint32_t sdst, const void* g, uint32_t bytes, uint32_t mb) {
    asm volatile("mbarrier.arrive.expect_tx.shared.b64 _, [%0], %1;" :: "r"(mb), "r"(bytes) : "memory");
    asm volatile("cp.async.bulk.shared::cluster.global.mbarrier::complete_tx::bytes [%0], [%1], %2, [%3];"
                 :: "r"(sdst), "l"(g), "r"(bytes), "r"(mb) : "memory");
}
__device__ __forceinline__ void mbar_wait(uint32_t m, uint32_t par) {
    uint32_t done;
    asm volatile("{.reg .pred p; mbarrier.try_wait.parity.acquire.cta.shared::cta.b64 p, [%1], %2; selp.b32 %0,1,0,p;}"
                 : "=r"(done) : "r"(m), "r"(par) : "memory");
    if (!done) {
        asm volatile("{.reg .pred P1;\nWL_%=:\n"
                     "mbarrier.try_wait.parity.acquire.cta.shared::cta.b64 P1, [%0], %1, 0x989680;\n"
                     "@P1 bra.uni WD_%=;\nbra.uni WL_%=;\nWD_%=:\n}"
                     :: "r"(m), "r"(par) : "memory");
    }
}
// single-writer monotone flags
__device__ __forceinline__ void flag_set(int* f, int v) {
    asm volatile("st.release.gpu.global.u32 [%0], %1;" :: "l"(f), "r"(v) : "memory");
}
__device__ __forceinline__ void poll_min8(const int* f, int tgt) {
    for (;;) {
        int m = 0x7fffffff;
#pragma unroll
        for (int r = 0; r < 8; r++) {
            int v;
            asm volatile("ld.acquire.gpu.global.u32 %0, [%1];" : "=r"(v) : "l"(f + r) : "memory");
            m = min(m, v);
        }
        if (m >= tgt) return;
        __nanosleep(64);
    }
}

// M=128 x N=128 gemm: one 16KB A chunk vs one 16KB W chunk
__device__ __forceinline__ void gemm_chunk(
    const char* smem, int aoff, int boff, float (&acc)[2][4][4],
    int wm, int wn, int a_ro, int a_h, int b_ro, int b_h)
{
    const __half* sA = (const __half*)(smem + aoff);
    const __half* sB = (const __half*)(smem + boff);
#pragma unroll
    for (int k16 = 0; k16 < 4; k16++) {
        uint32_t afr[2][4];
#pragma unroll
        for (int mi = 0; mi < 2; mi++) {
            int r = wm * 32 + mi * 16 + a_ro;
            int cch = (k16 * 2 + a_h) ^ (r & 7);
            uint32_t ad = (uint32_t)__cvta_generic_to_shared(sA + r * 64 + cch * 8);
            asm volatile("ldmatrix.sync.aligned.m8n8.x4.shared.b16 {%0,%1,%2,%3}, [%4];"
                         : "=r"(afr[mi][0]), "=r"(afr[mi][1]), "=r"(afr[mi][2]), "=r"(afr[mi][3])
                         : "r"(ad));
        }
        uint32_t bfr[2][4];
#pragma unroll
        for (int np = 0; np < 2; np++) {
            int r = wn * 32 + np * 16 + b_ro;
            int cch = (k16 * 2 + b_h) ^ (r & 7);
            uint32_t ad = (uint32_t)__cvta_generic_to_shared(sB + r * 64 + cch * 8);
            asm volatile("ldmatrix.sync.aligned.m8n8.x4.shared.b16 {%0,%1,%2,%3}, [%4];"
                         : "=r"(bfr[np][0]), "=r"(bfr[np][1]), "=r"(bfr[np][2]), "=r"(bfr[np][3])
                         : "r"(ad));
        }
#pragma unroll
        for (int mi = 0; mi < 2; mi++)
#pragma unroll
            for (int nj = 0; nj < 4; nj++) {
                uint32_t b0 = bfr[nj >> 1][(nj & 1) * 2 + 0];
                uint32_t b1 = bfr[nj >> 1][(nj & 1) * 2 + 1];
                asm volatile("mma.sync.aligned.m16n8k16.row.col.f32.f16.f16.f32 "
                             "{%0,%1,%2,%3}, {%4,%5,%6,%7}, {%8,%9}, {%0,%1,%2,%3};"
                             : "+f"(acc[mi][nj][0]), "+f"(acc[mi][nj][1]),
                               "+f"(acc[mi][nj][2]), "+f"(acc[mi][nj][3])
                             : "r"(afr[mi][0]), "r"(afr[mi][1]), "r"(afr[mi][2]), "r"(afr[mi][3]),
                               "r"(b0), "r"(b1));
            }
    }
}

template<bool FIN>
__device__ __forceinline__ void pw(float (&acc)[2][4][4], float* c, const float* biasr,
                                   char* smem, int stg, int lane, int wm, int wn)
{
    const int q = lane & 3;
    __half* hs = (__half*)(smem + stg);
    float*  fs = (float*)(smem + stg);
#pragma unroll
    for (int mi = 0; mi < 2; mi++) {
        int r0 = wm * 32 + mi * 16 + (lane >> 2);
#pragma unroll
        for (int us = 0; us < 2; us++)
#pragma unroll
            for (int ru = 0; ru < 2; ru++) {
                float gi = acc[mi][us*2+0][ru*2+0] + biasr[us*4+0];
                float gf = acc[mi][us*2+0][ru*2+1] + biasr[us*4+1];
                float gg = acc[mi][us*2+1][ru*2+0] + biasr[us*4+2];
                float go = acc[mi][us*2+1][ru*2+1] + biasr[us*4+3];
                int ci = mi * 4 + us * 2 + ru;
                float iv = siga_(gi), fv = siga_(gf), gv = tanha_(gg), ov = siga_(go);
                float cn = fv * c[ci] + iv * gv;
                c[ci] = cn;
                float h = ov * tanha_(cn);
                int row = r0 + ru * 8;
                int jl = wn * 8 + q + us * 4;
                if (FIN) fs[row * 32 + jl] = h;
                else     hs[row * 32 + jl] = __float2half(h);
            }
    }
}

__device__ __forceinline__ void gran(char* smem, int stg, char* gdst, int tid, int rank) {
    int row = tid >> 2, gg2 = tid & 3;
    uint4 v = *(uint4*)(smem + stg + row * 64 + gg2 * 16);
    int kcc = rank >> 1, g2 = ((rank & 1) << 2) | gg2;
    *(uint4*)(gdst + (size_t)kcc * CH + row * 128 + ((g2 ^ (row & 7)) << 4)) = v;
}

__global__ void __launch_bounds__(THREADS, 1)
k_lstm()
{
    extern __shared__ __align__(1024) char smem[];
    uint32_t sb = smem_u32(smem);
    const int tid = threadIdx.x, lane = tid & 31, warp = tid >> 5;
    const int wm = warp & 3, wn = warp >> 2;
    const int rank = blockIdx.x, ms = blockIdx.y;
    const int mbase = ms * 128, nbase = rank * 128;
    const int q = lane & 3;
    const int lg = lane >> 3, lr = lane & 7;
    const int a_ro = lr + ((lg & 1) << 3), a_h = lg >> 1;
    const int b_ro = lr + ((lg >> 1) << 3), b_h = lg & 1;
    const uint32_t MB = sb + SMB_OFF;
    const uint32_t mbW = MB + 48;
    int* f1 = g_f1 + ms * 8;
    int* f2 = g_f2 + ms * 8;
    int* fr = g_fr + ms * 8;

    if (tid == 0) {
#pragma unroll
        for (int i = 0; i < 6; i++) mbar_init(MB + i * 8, 1);
        mbar_init(mbW, 1);
    }
    __syncthreads();

    int uc[6] = {0, 0, 0, 0, 0, 0};
    float biasr[8], c[8];
    auto h1t = [&](int t) { return (char*)g_h1seq + ((size_t)t * 16 + ms) * TILE; };
    auto h2t = [&](int t) { return (char*)((t & 1) ? g_h2b : g_h2a) + (size_t)ms * TILE; };
    const char* zt = (const char*)g_zero + (size_t)ms * TILE;
    auto xt = [&](int t) { return (const char*)g_x16 + (size_t)(t * 16 + ms) * CH; };

    // ---- phase A setup ----
    if (tid == 0) {
        bulk_in(sb + SW_OFF, (char*)g_W0 + (size_t)rank * 81920, 81920, mbW);
        bulk_in(sb + RING_OFF + 4 * CH, xt(0), CH, MB + 32);
    }
#pragma unroll
    for (int nj = 0; nj < 4; nj++) {
        biasr[nj * 2 + 0] = g_b0[nbase + wn * 32 + nj * 8 + q * 2 + 0];
        biasr[nj * 2 + 1] = g_b0[nbase + wn * 32 + nj * 8 + q * 2 + 1];
    }
#pragma unroll
    for (int i = 0; i < 8; i++) c[i] = 0.f;
    mbar_wait(mbW, 0);
    __syncthreads();

    // ---- phase A: layer 0, K=320 ----
#pragma unroll 1
    for (int t = 0; t < T_; t++) {
        float acc[2][4][4];
#pragma unroll
        for (int mi = 0; mi < 2; mi++)
#pragma unroll
            for (int nj = 0; nj < 4; nj++)
#pragma unroll
                for (int e = 0; e < 4; e++) acc[mi][nj][e] = 0.f;
        int sx = 4 + (t & 1);
        mbar_wait(MB + sx * 8, uc[sx] & 1); uc[sx]++;
        gemm_chunk(smem, RING_OFF + sx * CH, SW_OFF + 0, acc, wm, wn, a_ro, a_h, b_ro, b_h);
        if (tid == 0) {
            if (t > 0) poll_min8(f1, t);
            const char* hs = (t == 0) ? zt : h1t(t - 1);
#pragma unroll
            for (int p = 0; p < 4; p++)
                bulk_in(sb + RING_OFF + p * CH, hs + p * CH, CH, MB + p * 8);
        }
#pragma unroll
        for (int kc = 0; kc < 4; kc++) {
            mbar_wait(MB + kc * 8, uc[kc] & 1); uc[kc]++;
            gemm_chunk(smem, RING_OFF + kc * CH, SW_OFF + (1 + kc) * CH, acc,
                       wm, wn, a_ro, a_h, b_ro, b_h);
        }
        __syncthreads();
        if (tid == 0 && t + 1 < T_)
            bulk_in(sb + RING_OFF + (4 + ((t + 1) & 1)) * CH, xt(t + 1), CH,
                    MB + (4 + ((t + 1) & 1)) * 8);
        pw<false>(acc, c, biasr, smem, STGA_OFF, lane, wm, wn);
        __syncthreads();
        gran(smem, STGA_OFF, h1t(t), tid, rank);
        __syncthreads();
        if (tid == 0) {
            asm volatile("fence.proxy.async;" ::: "memory");
            flag_set(f1 + rank, t + 1);
        }
    }

    // ---- phase boundary (local only) ----
    __syncthreads();
    if (tid == 0)
        bulk_in(sb + SW_OFF, (char*)g_W1 + (size_t)rank * 131072, 131072, mbW);
#pragma unroll
    for (int nj = 0; nj < 4; nj++) {
        biasr[nj * 2 + 0] = g_b1[nbase + wn * 32 + nj * 8 + q * 2 + 0];
        biasr[nj * 2 + 1] = g_b1[nbase + wn * 32 + nj * 8 + q * 2 + 1];
    }
#pragma unroll
    for (int i = 0; i < 8; i++) c[i] = 0.f;
    mbar_wait(mbW, 1);
    __syncthreads();

    // ---- phase B: layer 1, K=512 ----
#pragma unroll 1
    for (int t = 0; t < T_; t++) {
        bool fin = (t == T_ - 1);
        float acc[2][4][4];
#pragma unroll
        for (int mi = 0; mi < 2; mi++)
#pragma unroll
            for (int nj = 0; nj < 4; nj++)
#pragma unroll
                for (int e = 0; e < 4; e++) acc[mi][nj][e] = 0.f;
        if (tid == 0) {
            poll_min8(f1, t + 1);
#pragma unroll
            for (int p = 0; p < 4; p++)
                bulk_in(sb + RING_OFF + p * CH, h1t(t) + p * CH, CH, MB + p * 8);
        }
#pragma unroll
        for (int kc = 0; kc < 4; kc++) {
            mbar_wait(MB + kc * 8, uc[kc] & 1); uc[kc]++;
            gemm_chunk(smem, RING_OFF + kc * CH, SW_OFF + kc * CH, acc,
                       wm, wn, a_ro, a_h, b_ro, b_h);
        }
        __syncthreads();
        if (tid == 0) {
            if (t > 0) poll_min8(f2, t);
            const char* hs = (t == 0) ? zt : h2t(t - 1);
            bulk_in(sb + RING_OFF + 4 * CH, hs + 0 * CH, CH, MB + 32);
            bulk_in(sb + RING_OFF + 5 * CH, hs + 1 * CH, CH, MB + 40);
            bulk_in(sb + RING_OFF + 2 * CH, hs + 2 * CH, CH, MB + 16);
            bulk_in(sb + RING_OFF + 3 * CH, hs + 3 * CH, CH, MB + 24);
        }
        mbar_wait(MB + 32, uc[4] & 1); uc[4]++;
        gemm_chunk(smem, RING_OFF + 4 * CH, SW_OFF + 4 * CH, acc, wm, wn, a_ro, a_h, b_ro, b_h);
        mbar_wait(MB + 40, uc[5] & 1); uc[5]++;
        gemm_chunk(smem, RING_OFF + 5 * CH, SW_OFF + 5 * CH, acc, wm, wn, a_ro, a_h, b_ro, b_h);
        mbar_wait(MB + 16, uc[2] & 1); uc[2]++;
        gemm_chunk(smem, RING_OFF + 2 * CH, SW_OFF + 6 * CH, acc, wm, wn, a_ro, a_h, b_ro, b_h);
        mbar_wait(MB + 24, uc[3] & 1); uc[3]++;
        gemm_chunk(smem, RING_OFF + 3 * CH, SW_OFF + 7 * CH, acc, wm, wn, a_ro, a_h, b_ro, b_h);
        __syncthreads();
        if (tid == 0) flag_set(fr + rank, t + 1);   // global h2(t-1)/zero reads complete
        if (fin) {
            pw<true>(acc, c, biasr, smem, STGB_OFF, lane, wm, wn);
            __syncthreads();
            float* fd = g_h2f + (size_t)mbase * H_;
#pragma unroll
            for (int p = 0; p < 8; p++) {
                int row = p * 16 + (tid >> 5);
                int cc = tid & 31;
                fd[(size_t)row * H_ + rank * 32 + cc] =
                    *(float*)(smem + STGB_OFF + (row * 32 + cc) * 4);
            }
        } else {
            pw<false>(acc, c, biasr, smem, STGB_OFF, lane, wm, wn);
            if (tid == 0 && t > 0) poll_min8(fr, t);   // readers of h2(t-2) done
            __syncthreads();
            gran(smem, STGB_OFF, h2t(t), tid, rank);
            __syncthreads();
            if (tid == 0) {
                asm volatile("fence.proxy.async;" ::: "memory");
                flag_set(f2 + rank, t + 1);
            }
        }
    }
}

__global__ void k_fc(const float* __restrict__ Wfc, const float* __restrict__ bfc,
                     float* __restrict__ out) {
    int b = blockIdx.x;
    int o = threadIdx.y;
    int lane = threadIdx.x;
    const float* hr = g_h2f + (size_t)b * H_;
    const float* wr = Wfc + (size_t)o * H_;
    float s = 0.f;
    for (int j = lane; j < H_; j += 32) s += hr[j] * wr[j];
#pragma unroll
    for (int off = 16; off; off >>= 1) s += __shfl_xor_sync(0xffffffffu, s, off);
    if (lane == 0) out[b * 6 + o] = s + bfc[o];
}

extern "C" void kernel_launch(void* const* d_in, const int* in_sizes, int n_in,
                              void* d_out, int out_size) {
    const float* x     = (const float*)d_in[0];
    const float* W_ih0 = (const float*)d_in[1];
    const float* W_hh0 = (const float*)d_in[2];
    const float* b_ih0 = (const float*)d_in[3];
    const float* b_hh0 = (const float*)d_in[4];
    const float* W_ih1 = (const float*)d_in[5];
    const float* W_hh1 = (const float*)d_in[6];
    const float* b_ih1 = (const float*)d_in[7];
    const float* b_hh1 = (const float*)d_in[8];
    const float* W_fc  = (const float*)d_in[9];
    const float* b_fc  = (const float*)d_in[10];

    cudaFuncSetAttribute(k_lstm, cudaFuncAttributeMaxDynamicSharedMemorySize, SMEM_TOTAL);

    k_init<<<256, 256>>>();
    k_packx<<<4096, 256>>>(x);
    k_pack0<<<640, 256>>>(W_ih0, W_hh0, b_ih0, b_hh0);
    k_pack1<<<1024, 256>>>(W_ih1, W_hh1, b_ih1, b_hh1);

    k_lstm<<<dim3(8, 16), THREADS, SMEM_TOTAL>>>();

    k_fc<<<B_, dim3(32, 6)>>>(W_fc, b_fc, (float*)d_out);
}

// round 17
// speedup vs baseline: 2.0989x; 1.2073x over previous
#include <cuda_runtime.h>
#include <cuda_fp16.h>
#include <cstdint>
#include <cstddef>

#define B_ 2048
#define T_ 200
#define D_ 4
#define H_ 256
#define G_ 1024
#define THREADS 512
#define CH 16384
#define TILE 65536

// smem layout
#define SW_OFF    0                   // W: phase A 5 chunks (80KB), phase B 8 chunks (128KB)
#define STGA_OFF  81920               // phase A staging (inside unused W region)
#define RING_OFF  131072              // 6 slots * 16KB
#define STGB_OFF  (RING_OFF + 4*CH)   // phase B staging = slot 4 region
#define SMB_OFF   (RING_OFF + 6*CH)   // 6 slot mbars + W mbar
#define SMEM_TOTAL (SMB_OFF + 64)

__device__ __align__(128) __half g_W0[G_ * 320];
__device__ __align__(128) float  g_b0[G_];
__device__ __align__(128) __half g_W1[G_ * 512];
__device__ __align__(128) float  g_b1[G_];
__device__ __align__(128) __half g_x16[(size_t)T_ * B_ * 64];
__device__ __align__(128) __half g_zero[B_ * H_];
__device__ __align__(128) __half g_h1seq[(size_t)T_ * B_ * H_];
__device__ __align__(128) __half g_h2a[B_ * H_];
__device__ __align__(128) __half g_h2b[B_ * H_];
__device__ __align__(128) float  g_h2f[B_ * H_];
__device__ int g_f1[16 * 8];   // layer0 steps completed per (ms, rank)
__device__ int g_f2[16 * 8];   // layer1 steps completed
__device__ int g_fr[16 * 8];   // layer1 h-read steps completed

__global__ void k_init() {
    int s = gridDim.x * blockDim.x;
    int i0 = blockIdx.x * blockDim.x + threadIdx.x;
    for (int i = i0; i < B_ * H_; i += s) g_zero[i] = __float2half(0.f);
    if (i0 < 16 * 8) { g_f1[i0] = 0; g_f2[i0] = 0; g_fr[i0] = 0; }
}
__device__ __forceinline__ size_t swoff(int r, int k) {
    int kc = k >> 6, cc = k & 63, g = cc >> 3, e = cc & 7;
    return (size_t)kc * CH + r * 128 + ((g ^ (r & 7)) << 4) + e * 2;
}
__device__ __forceinline__ int col2row(int n) {
    int c = n & 31;
    int j = (n >> 5) * 8 + ((c >> 4) << 2) + ((c >> 1) & 3);
    int blk = (c >> 3) & 1, e = c & 1;
    int g = blk ? (e ? 3 : 2) : (e ? 1 : 0);
    return g * H_ + j;
}
__global__ void k_packx(const float* __restrict__ x) {
    int s = gridDim.x * blockDim.x;
    const int N = T_ * B_ * 64;
    for (int i = blockIdx.x * blockDim.x + threadIdx.x; i < N; i += s) {
        int k = i & 63, b = (i >> 6) & (B_ - 1), t = i >> 17;
        float v = (k < D_) ? x[((size_t)b * T_ + t) * D_ + k] : 0.f;
        int ms = b >> 7, r = b & 127;
        *(__half*)((char*)g_x16 + (size_t)(t * 16 + ms) * CH + swoff(r, k)) = __float2half(v);
    }
}
__global__ void k_pack0(const float* __restrict__ Wi, const float* __restrict__ Wh,
                        const float* __restrict__ bi, const float* __restrict__ bh) {
    int s = gridDim.x * blockDim.x;
    const int N = G_ * 320;
    for (int i = blockIdx.x * blockDim.x + threadIdx.x; i < N; i += s) {
        int n = i / 320, k = i % 320;
        int orow = col2row(n);
        int rank = n >> 7, r = n & 127;
        float v = (k < 64) ? ((k < D_) ? Wi[orow * D_ + k] : 0.f) : Wh[orow * H_ + (k - 64)];
        *(__half*)((char*)g_W0 + (size_t)rank * 81920 + swoff(r, k)) = __float2half(v);
        if (k == 0) g_b0[n] = bi[orow] + bh[orow];
    }
}
__global__ void k_pack1(const float* __restrict__ Wi, const float* __restrict__ Wh,
                        const float* __restrict__ bi, const float* __restrict__ bh) {
    int s = gridDim.x * blockDim.x;
    for (int i = blockIdx.x * blockDim.x + threadIdx.x; i < G_ * 512; i += s) {
        int n = i >> 9, k = i & 511;
        int orow = col2row(n);
        int rank = n >> 7, r = n & 127;
        float v = (k < H_) ? Wi[orow * H_ + k] : Wh[orow * H_ + (k - H_)];
        *(__half*)((char*)g_W1 + (size_t)rank * 131072 + swoff(r, k)) = __float2half(v);
        if (k == 0) g_b1[n] = bi[orow] + bh[orow];
    }
}

__device__ __forceinline__ uint32_t smem_u32(const void* p) {
    uint32_t a;
    asm("{ .reg .u64 t; cvta.to.shared.u64 t, %1; cvt.u32.u64 %0, t; }" : "=r"(a) : "l"(p));
    return a;
}
__device__ __forceinline__ float tanha_(float x) {
    float r; asm("tanh.approx.f32 %0, %1;" : "=f"(r) : "f"(x));
    return r;
}
__device__ __forceinline__ float siga_(float x) { return __fmaf_rn(tanha_(0.5f * x), 0.5f, 0.5f); }
__device__ __forceinline__ void mbar_init(uint32_t m, uint32_t c) {
    asm volatile("mbarrier.init.shared.b64 [%0], %1;" :: "r"(m), "r"(c) : "memory");
}
__device__ __forceinline__ void bulk_in(uint32_t sdst, const void* g, uint32_t bytes, uint32_t mb) {
    asm volatile("mbarrier.arrive.expect_tx.shared.b64 _, [%0], %1;" :: "r"(mb), "r"(bytes) : "memory");
    asm volatile("cp.async.bulk.shared::cluster.global.mbarrier::complete_tx::bytes [%0], [%1], %2, [%3];"
                 :: "r"(sdst), "l"(g), "r"(bytes), "r"(mb) : "memory");
}
__device__ __forceinline__ void mbar_wait(uint32_t m, uint32_t par) {
    uint32_t done;
    asm volatile("{.reg .pred p; mbarrier.try_wait.parity.acquire.cta.shared::cta.b64 p, [%1], %2; selp.b32 %0,1,0,p;}"
                 : "=r"(done) : "r"(m), "r"(par) : "memory");
    if (!done) {
        asm volatile("{.reg .pred P1;\nWL_%=:\n"
                     "mbarrier.try_wait.parity.acquire.cta.shared::cta.b64 P1, [%0], %1, 0x989680;\n"
                     "@P1 bra.uni WD_%=;\nbra.uni WL_%=;\nWD_%=:\n}"
                     :: "r"(m), "r"(par) : "memory");
    }
}
__device__ __forceinline__ void flag_set(int* f, int v) {
    asm volatile("st.release.gpu.global.u32 [%0], %1;" :: "l"(f), "r"(v) : "memory");
}
__device__ __forceinline__ int ld_acq(const int* p) {
    int v;
    asm volatile("ld.acquire.gpu.global.u32 %0, [%1];" : "=r"(v) : "l"(p) : "memory");
    return v;
}
// wait for ranks 2p, 2p+1 to reach tgt (producers of chunk p)
__device__ __forceinline__ void poll2(const int* f, int p, int tgt) {
    const int* a = f + 2 * p;
    for (;;) {
        int m = min(ld_acq(a), ld_acq(a + 1));
        if (m >= tgt) return;
        __nanosleep(64);
    }
}
__device__ __forceinline__ void poll_min8(const int* f, int tgt) {
    for (;;) {
        int m = 0x7fffffff;
#pragma unroll
        for (int r = 0; r < 8; r++) m = min(m, ld_acq(f + r));
        if (m >= tgt) return;
        __nanosleep(64);
    }
}

// M=128 x N=128 gemm: one 16KB A chunk vs one 16KB W chunk
__device__ __forceinline__ void gemm_chunk(
    const char* smem, int aoff, int boff, float (&acc)[2][4][4],
    int wm, int wn, int a_ro, int a_h, int b_ro, int b_h)
{
    const __half* sA = (const __half*)(smem + aoff);
    const __half* sB = (const __half*)(smem + boff);
#pragma unroll
    for (int k16 = 0; k16 < 4; k16++) {
        uint32_t afr[2][4];
#pragma unroll
        for (int mi = 0; mi < 2; mi++) {
            int r = wm * 32 + mi * 16 + a_ro;
            int cch = (k16 * 2 + a_h) ^ (r & 7);
            uint32_t ad = (uint32_t)__cvta_generic_to_shared(sA + r * 64 + cch * 8);
            asm volatile("ldmatrix.sync.aligned.m8n8.x4.shared.b16 {%0,%1,%2,%3}, [%4];"
                         : "=r"(afr[mi][0]), "=r"(afr[mi][1]), "=r"(afr[mi][2]), "=r"(afr[mi][3])
                         : "r"(ad));
        }
        uint32_t bfr[2][4];
#pragma unroll
        for (int np = 0; np < 2; np++) {
            int r = wn * 32 + np * 16 + b_ro;
            int cch = (k16 * 2 + b_h) ^ (r & 7);
            uint32_t ad = (uint32_t)__cvta_generic_to_shared(sB + r * 64 + cch * 8);
            asm volatile("ldmatrix.sync.aligned.m8n8.x4.shared.b16 {%0,%1,%2,%3}, [%4];"
                         : "=r"(bfr[np][0]), "=r"(bfr[np][1]), "=r"(bfr[np][2]), "=r"(bfr[np][3])
                         : "r"(ad));
        }
#pragma unroll
        for (int mi = 0; mi < 2; mi++)
#pragma unroll
            for (int nj = 0; nj < 4; nj++) {
                uint32_t b0 = bfr[nj >> 1][(nj & 1) * 2 + 0];
                uint32_t b1 = bfr[nj >> 1][(nj & 1) * 2 + 1];
                asm volatile("mma.sync.aligned.m16n8k16.row.col.f32.f16.f16.f32 "
                             "{%0,%1,%2,%3}, {%4,%5,%6,%7}, {%8,%9}, {%0,%1,%2,%3};"
                             : "+f"(acc[mi][nj][0]), "+f"(acc[mi][nj][1]),
                               "+f"(acc[mi][nj][2]), "+f"(acc[mi][nj][3])
                             : "r"(afr[mi][0]), "r"(afr[mi][1]), "r"(afr[mi][2]), "r"(afr[mi][3]),
                               "r"(b0), "r"(b1));
            }
    }
}

template<bool FIN>
__device__ __forceinline__ void pw(float (&acc)[2][4][4], float* c, const float* biasr,
                                   char* smem, int stg, int lane, int wm, int wn)
{
    const int q = lane & 3;
    __half* hs = (__half*)(smem + stg);
    float*  fs = (float*)(smem + stg);
#pragma unroll
    for (int mi = 0; mi < 2; mi++) {
        int r0 = wm * 32 + mi * 16 + (lane >> 2);
#pragma unroll
        for (int us = 0; us < 2; us++)
#pragma unroll
            for (int ru = 0; ru < 2; ru++) {
                float gi = acc[mi][us*2+0][ru*2+0] + biasr[us*4+0];
                float gf = acc[mi][us*2+0][ru*2+1] + biasr[us*4+1];
                float gg = acc[mi][us*2+1][ru*2+0] + biasr[us*4+2];
                float go = acc[mi][us*2+1][ru*2+1] + biasr[us*4+3];
                int ci = mi * 4 + us * 2 + ru;
                float iv = siga_(gi), fv = siga_(gf), gv = tanha_(gg), ov = siga_(go);
                float cn = fv * c[ci] + iv * gv;
                c[ci] = cn;
                float h = ov * tanha_(cn);
                int row = r0 + ru * 8;
                int jl = wn * 8 + q + us * 4;
                if (FIN) fs[row * 32 + jl] = h;
                else     hs[row * 32 + jl] = __float2half(h);
            }
    }
}

__device__ __forceinline__ void gran(char* smem, int stg, char* gdst, int tid, int rank) {
    int row = tid >> 2, gg2 = tid & 3;
    uint4 v = *(uint4*)(smem + stg + row * 64 + gg2 * 16);
    int kcc = rank >> 1, g2 = ((rank & 1) << 2) | gg2;
    *(uint4*)(gdst + (size_t)kcc * CH + row * 128 + ((g2 ^ (row & 7)) << 4)) = v;
}

__global__ void __launch_bounds__(THREADS, 1)
k_lstm()
{
    extern __shared__ __align__(1024) char smem[];
    uint32_t sb = smem_u32(smem);
    const int tid = threadIdx.x, lane = tid & 31, warp = tid >> 5;
    const int wm = warp & 3, wn = warp >> 2;
    const int rank = blockIdx.x, ms = blockIdx.y;
    const int mbase = ms * 128, nbase = rank * 128;
    const int q = lane & 3;
    const int lg = lane >> 3, lr = lane & 7;
    const int a_ro = lr + ((lg & 1) << 3), a_h = lg >> 1;
    const int b_ro = lr + ((lg >> 1) << 3), b_h = lg & 1;
    const uint32_t MB = sb + SMB_OFF;
    const uint32_t mbW = MB + 48;
    int* f1 = g_f1 + ms * 8;
    int* f2 = g_f2 + ms * 8;
    int* fr = g_fr + ms * 8;

    if (tid == 0) {
#pragma unroll
        for (int i = 0; i < 6; i++) mbar_init(MB + i * 8, 1);
        mbar_init(mbW, 1);
    }
    __syncthreads();

    int uc[6] = {0, 0, 0, 0, 0, 0};
    float biasr[8], c[8];
    auto h1t = [&](int t) { return (char*)g_h1seq + ((size_t)t * 16 + ms) * TILE; };
    auto h2t = [&](int t) { return (char*)((t & 1) ? g_h2b : g_h2a) + (size_t)ms * TILE; };
    const char* zt = (const char*)g_zero + (size_t)ms * TILE;
    auto xt = [&](int t) { return (const char*)g_x16 + (size_t)(t * 16 + ms) * CH; };

    // ---- phase A setup ----
    if (tid == 0) {
        bulk_in(sb + SW_OFF, (char*)g_W0 + (size_t)rank * 81920, 81920, mbW);
        bulk_in(sb + RING_OFF + 4 * CH, xt(0), CH, MB + 32);
    }
#pragma unroll
    for (int nj = 0; nj < 4; nj++) {
        biasr[nj * 2 + 0] = g_b0[nbase + wn * 32 + nj * 8 + q * 2 + 0];
        biasr[nj * 2 + 1] = g_b0[nbase + wn * 32 + nj * 8 + q * 2 + 1];
    }
#pragma unroll
    for (int i = 0; i < 8; i++) c[i] = 0.f;
    mbar_wait(mbW, 0);
    __syncthreads();

    // ---- phase A: layer 0, K=320 ----
#pragma unroll 1
    for (int t = 0; t < T_; t++) {
        float acc[2][4][4];
#pragma unroll
        for (int mi = 0; mi < 2; mi++)
#pragma unroll
            for (int nj = 0; nj < 4; nj++)
#pragma unroll
                for (int e = 0; e < 4; e++) acc[mi][nj][e] = 0.f;
        int sx = 4 + (t & 1);
        mbar_wait(MB + sx * 8, uc[sx] & 1); uc[sx]++;
        gemm_chunk(smem, RING_OFF + sx * CH, SW_OFF + 0, acc, wm, wn, a_ro, a_h, b_ro, b_h);
        if (tid == 0) {
            const char* hs = (t == 0) ? zt : h1t(t - 1);
#pragma unroll
            for (int p = 0; p < 4; p++) {
                if (t > 0) poll2(f1, p, t);
                bulk_in(sb + RING_OFF + p * CH, hs + p * CH, CH, MB + p * 8);
            }
        }
#pragma unroll
        for (int kc = 0; kc < 4; kc++) {
            mbar_wait(MB + kc * 8, uc[kc] & 1); uc[kc]++;
            gemm_chunk(smem, RING_OFF + kc * CH, SW_OFF + (1 + kc) * CH, acc,
                       wm, wn, a_ro, a_h, b_ro, b_h);
        }
        __syncthreads();
        if (tid == 0 && t + 1 < T_)
            bulk_in(sb + RING_OFF + (4 + ((t + 1) & 1)) * CH, xt(t + 1), CH,
                    MB + (4 + ((t + 1) & 1)) * 8);
        pw<false>(acc, c, biasr, smem, STGA_OFF, lane, wm, wn);
        __syncthreads();
        gran(smem, STGA_OFF, h1t(t), tid, rank);
        __syncthreads();
        if (tid == 0) {
            asm volatile("fence.proxy.async;" ::: "memory");
            flag_set(f1 + rank, t + 1);
        }
    }

    // ---- phase boundary (local only) ----
    __syncthreads();
    if (tid == 0)
        bulk_in(sb + SW_OFF, (char*)g_W1 + (size_t)rank * 131072, 131072, mbW);
#pragma unroll
    for (int nj = 0; nj < 4; nj++) {
        biasr[nj * 2 + 0] = g_b1[nbase + wn * 32 + nj * 8 + q * 2 + 0];
        biasr[nj * 2 + 1] = g_b1[nbase + wn * 32 + nj * 8 + q * 2 + 1];
    }
#pragma unroll
    for (int i = 0; i < 8; i++) c[i] = 0.f;
    mbar_wait(mbW, 1);
    __syncthreads();

    // ---- phase B: layer 1, K=512 ----
#pragma unroll 1
    for (int t = 0; t < T_; t++) {
        bool fin = (t == T_ - 1);
        float acc[2][4][4];
#pragma unroll
        for (int mi = 0; mi < 2; mi++)
#pragma unroll
            for (int nj = 0; nj < 4; nj++)
#pragma unroll
                for (int e = 0; e < 4; e++) acc[mi][nj][e] = 0.f;
        if (tid == 0) {
#pragma unroll
            for (int p = 0; p < 4; p++) {
                poll2(f1, p, t + 1);
                bulk_in(sb + RING_OFF + p * CH, h1t(t) + p * CH, CH, MB + p * 8);
            }
        }
#pragma unroll
        for (int kc = 0; kc < 4; kc++) {
            mbar_wait(MB + kc * 8, uc[kc] & 1); uc[kc]++;
            gemm_chunk(smem, RING_OFF + kc * CH, SW_OFF + kc * CH, acc,
                       wm, wn, a_ro, a_h, b_ro, b_h);
        }
        __syncthreads();
        if (tid == 0) {
            const char* hs = (t == 0) ? zt : h2t(t - 1);
            const int slot[4] = {4, 5, 2, 3};
            const uint32_t mba[4] = {MB + 32, MB + 40, MB + 16, MB + 24};
#pragma unroll
            for (int p = 0; p < 4; p++) {
                if (t > 0) poll2(f2, p, t);
                bulk_in(sb + RING_OFF + slot[p] * CH, hs + p * CH, CH, mba[p]);
            }
        }
        mbar_wait(MB + 32, uc[4] & 1); uc[4]++;
        gemm_chunk(smem, RING_OFF + 4 * CH, SW_OFF + 4 * CH, acc, wm, wn, a_ro, a_h, b_ro, b_h);
        mbar_wait(MB + 40, uc[5] & 1); uc[5]++;
        gemm_chunk(smem, RING_OFF + 5 * CH, SW_OFF + 5 * CH, acc, wm, wn, a_ro, a_h, b_ro, b_h);
        mbar_wait(MB + 16, uc[2] & 1); uc[2]++;
        gemm_chunk(smem, RING_OFF + 2 * CH, SW_OFF + 6 * CH, acc, wm, wn, a_ro, a_h, b_ro, b_h);
        mbar_wait(MB + 24, uc[3] & 1); uc[3]++;
        gemm_chunk(smem, RING_OFF + 3 * CH, SW_OFF + 7 * CH, acc, wm, wn, a_ro, a_h, b_ro, b_h);
        __syncthreads();
        if (tid == 0) flag_set(fr + rank, t + 1);
        if (fin) {
            pw<true>(acc, c, biasr, smem, STGB_OFF, lane, wm, wn);
            __syncthreads();
            float* fd = g_h2f + (size_t)mbase * H_;
#pragma unroll
            for (int p = 0; p < 8; p++) {
                int row = p * 16 + (tid >> 5);
                int cc = tid & 31;
                fd[(size_t)row * H_ + rank * 32 + cc] =
                    *(float*)(smem + STGB_OFF + (row * 32 + cc) * 4);
            }
        } else {
            pw<false>(acc, c, biasr, smem, STGB_OFF, lane, wm, wn);
            if (tid == 0 && t > 0) poll_min8(fr, t);
            __syncthreads();
            gran(smem, STGB_OFF, h2t(t), tid, rank);
            __syncthreads();
            if (tid == 0) {
                asm volatile("fence.proxy.async;" ::: "memory");
                flag_set(f2 + rank, t + 1);
            }
        }
    }
}

__global__ void k_fc(const float* __restrict__ Wfc, const float* __restrict__ bfc,
                     float* __restrict__ out) {
    int b = blockIdx.x;
    int o = threadIdx.y;
    int lane = threadIdx.x;
    const float* hr = g_h2f + (size_t)b * H_;
    const float* wr = Wfc + (size_t)o * H_;
    float s = 0.f;
    for (int j = lane; j < H_; j += 32) s += hr[j] * wr[j];
#pragma unroll
    for (int off = 16; off; off >>= 1) s += __shfl_xor_sync(0xffffffffu, s, off);
    if (lane == 0) out[b * 6 + o] = s + bfc[o];
}

extern "C" void kernel_launch(void* const* d_in, const int* in_sizes, int n_in,
                              void* d_out, int out_size) {
    const float* x     = (const float*)d_in[0];
    const float* W_ih0 = (const float*)d_in[1];
    const float* W_hh0 = (const float*)d_in[2];
    const float* b_ih0 = (const float*)d_in[3];
    const float* b_hh0 = (const float*)d_in[4];
    const float* W_ih1 = (const float*)d_in[5];
    const float* W_hh1 = (const float*)d_in[6];
    const float* b_ih1 = (const float*)d_in[7];
    const float* b_hh1 = (const float*)d_in[8];
    const float* W_fc  = (const float*)d_in[9];
    const float* b_fc  = (const float*)d_in[10];

    cudaFuncSetAttribute(k_lstm, cudaFuncAttributeMaxDynamicSharedMemorySize, SMEM_TOTAL);

    k_init<<<256, 256>>>();
    k_packx<<<4096, 256>>>(x);
    k_pack0<<<640, 256>>>(W_ih0, W_hh0, b_ih0, b_hh0);
    k_pack1<<<1024, 256>>>(W_ih1, W_hh1, b_ih1, b_hh1);

    k_lstm<<<dim3(8, 16), THREADS, SMEM_TOTAL>>>();

    k_fc<<<B_, dim3(32, 6)>>>(W_fc, b_fc, (float*)d_out);
}